// round 14
// baseline (speedup 1.0000x reference)
#include <cuda_runtime.h>
#include <cuda_fp16.h>
#include <cstdint>

#define MAXN 50000
#define MAXE 800000

#define GDC_LAUNCH() asm volatile("griddepcontrol.launch_dependents;" ::: "memory")
#define GDC_WAIT()   asm volatile("griddepcontrol.wait;" ::: "memory")

// ================= device scratch =================
struct __align__(8) Edge8 { int row; __half2 c; };   // c = (dis[row], c2)

__device__ __half g_xpeh[MAXN * 256];
__device__ __half g_a0  [MAXN * 256];
__device__ __half g_a1  [MAXN * 256];
__device__ __half g_xmh [MAXN * 128];
__device__ __half g_wb  [256 * 256];
__device__ __half g_ws  [4][128 * 256];
__device__ int   g_cnt [2 * MAXN];
__device__ int   g_off0[MAXN + 1];
__device__ int   g_off1[MAXN + 1];
__device__ int   g_cur0[MAXN];
__device__ int   g_cur1[MAXN];
__device__ float g_dis0[MAXN];
__device__ float g_dis1[MAXN];
__device__ Edge8 g_ent0[MAXE];
__device__ Edge8 g_ent1[MAXE];

// ================= batched graph preprocessing =================
__global__ void k_count2(const int* __restrict__ c0, const int* __restrict__ c1,
                         int* __restrict__ cnt0, int* __restrict__ cnt1, int e) {
    int i = blockIdx.x * blockDim.x + threadIdx.x;
    const int* col = blockIdx.y ? c1 : c0;
    int* cnt = blockIdx.y ? cnt1 : cnt0;
    if (i < e) atomicAdd(&cnt[col[i]], 1);
}
__global__ void k_scan2(const int* __restrict__ cnt0, const int* __restrict__ cnt1,
                        int* __restrict__ off0, int* __restrict__ off1,
                        int* __restrict__ cur0, int* __restrict__ cur1,
                        float* __restrict__ dis0, float* __restrict__ dis1, int n) {
    __shared__ int s[1024];
    const int* cnt = blockIdx.x ? cnt1 : cnt0;
    int* off = blockIdx.x ? off1 : off0;
    int* cur = blockIdx.x ? cur1 : cur0;
    float* dis = blockIdx.x ? dis1 : dis0;
    int t = threadIdx.x;
    int chunk = (n + 1023) >> 10;
    int b = t * chunk;
    int e = min(b + chunk, n);
    int sum = 0;
    for (int i = b; i < e; i++) sum += cnt[i];
    s[t] = sum;
    __syncthreads();
    for (int o = 1; o < 1024; o <<= 1) {
        int v = (t >= o) ? s[t - o] : 0;
        __syncthreads();
        s[t] += v;
        __syncthreads();
    }
    int base = s[t] - sum;
    for (int i = b; i < e; i++) {
        int c = cnt[i];
        off[i] = base; cur[i] = base; base += c;
        dis[i] = rsqrtf((float)(c + 1));
    }
    if (t == 1023) off[n] = s[1023];
}
__global__ void k_fill2(const int* __restrict__ ei0, const float* __restrict__ ea0,
                        const int* __restrict__ ei1, const float* __restrict__ ea1,
                        const float* __restrict__ dis0, const float* __restrict__ dis1,
                        int* __restrict__ cur0, int* __restrict__ cur1,
                        Edge8* __restrict__ ent0, Edge8* __restrict__ ent1, int e) {
    int i = blockIdx.x * blockDim.x + threadIdx.x;
    if (i >= e) return;
    const int* ei = blockIdx.y ? ei1 : ei0;
    const float* attr = blockIdx.y ? ea1 : ea0;
    const float* dis = blockIdx.y ? dis1 : dis0;
    int* cur = blockIdx.y ? cur1 : cur0;
    Edge8* ent = blockIdx.y ? ent1 : ent0;
    int r = ei[i], c = ei[e + i];
    float a = attr[i];
    float c2 = (a > 0.f) ? fminf(rsqrtf(a), 1.f) : 0.f;
    Edge8 rec;
    rec.row = r;
    rec.c = __floats2half2_rn(dis[r], c2);
    int p = atomicAdd(&cur[c], 1);
    ent[p] = rec;
}

// ================= weight prep ======================
__global__ void k_wtcat(const float* __restrict__ w1, const float* __restrict__ w2,
                        __half* __restrict__ w) {
    int idx = blockIdx.x * blockDim.x + threadIdx.x;
    if (idx >= 256 * 256) return;
    int n = idx >> 8, k = idx & 255;
    float v = 0.f;
    if (k < 226) v = (n < 128) ? w1[k * 128 + n] : w2[k * 128 + (n - 128)];
    w[idx] = __float2half_rn(v);
}
__global__ void k_wtstk4(const float* __restrict__ w10, const float* __restrict__ w20,
                         const float* __restrict__ w11, const float* __restrict__ w21,
                         const float* __restrict__ w12, const float* __restrict__ w22,
                         const float* __restrict__ w13, const float* __restrict__ w23,
                         __half* __restrict__ w) {
    int idx = blockIdx.x * blockDim.x + threadIdx.x;
    if (idx >= 128 * 256) return;
    int g = blockIdx.y;
    const float* w1 = (g == 0) ? w10 : (g == 1) ? w11 : (g == 2) ? w12 : w13;
    const float* w2 = (g == 0) ? w20 : (g == 1) ? w21 : (g == 2) ? w22 : w23;
    int n = idx >> 8, k = idx & 255;
    float v = (k < 128) ? w1[k * 128 + n] : w2[(k - 128) * 128 + n];
    w[g * 32768 + idx] = __float2half_rn(v);
}

// ================= common PTX helpers =========================
__device__ __forceinline__ uint32_t smem_u32(const void* p) {
    uint32_t a;
    asm("{ .reg .u64 t; cvta.to.shared.u64 t, %1; cvt.u32.u64 %0, t; }" : "=r"(a) : "l"(p));
    return a;
}
__device__ __forceinline__ void cp16(uint32_t dst, const void* src) {
    asm volatile("cp.async.cg.shared.global [%0], [%1], 16;" :: "r"(dst), "l"(src));
}
__device__ __forceinline__ void cp_commit() { asm volatile("cp.async.commit_group;"); }
template <int W> __device__ __forceinline__ void cp_wait() {
    asm volatile("cp.async.wait_group %0;" :: "n"(W));
}
__device__ __forceinline__ void ldm_x4(uint32_t* r, uint32_t addr) {
    asm volatile("ldmatrix.sync.aligned.m8n8.x4.shared.b16 {%0,%1,%2,%3}, [%4];"
                 : "=r"(r[0]), "=r"(r[1]), "=r"(r[2]), "=r"(r[3]) : "r"(addr));
}
__device__ __forceinline__ void mma16816(float* c, const uint32_t* a, uint32_t b0, uint32_t b1) {
    asm volatile(
        "mma.sync.aligned.m16n8k16.row.col.f32.f16.f16.f32 "
        "{%0,%1,%2,%3}, {%4,%5,%6,%7}, {%8,%9}, {%0,%1,%2,%3};"
        : "+f"(c[0]), "+f"(c[1]), "+f"(c[2]), "+f"(c[3])
        : "r"(a[0]), "r"(a[1]), "r"(a[2]), "r"(a[3]), "r"(b0), "r"(b1));
}
__device__ __forceinline__ float4 ld_half4(const __half* p) {
    uint2 raw = *reinterpret_cast<const uint2*>(p);
    __half2 h0 = *reinterpret_cast<const __half2*>(&raw.x);
    __half2 h1 = *reinterpret_cast<const __half2*>(&raw.y);
    float2 f0 = __half22float2(h0), f1 = __half22float2(h1);
    return make_float4(f0.x, f0.y, f1.x, f1.y);
}

// ================= stage B: fused A-construct + HMMA GEMM ==============
// PDL: A construction (from inputs x/pe) runs pre-wait; B (wb, written by
// same-stream predecessor k_wtcat) is loaded post-wait.
#define BF_A 65536
#define BF_B 16384
#define SMEM_BF (BF_A + 2 * BF_B)   // 98304

__global__ void __launch_bounds__(256, 2) k_gemmBF(
    const float* __restrict__ x, const float* __restrict__ pe,
    const __half* __restrict__ wb, __half* __restrict__ xpe, int M) {
    extern __shared__ char sm[];
    const int tid  = threadIdx.x;
    const int lane = tid & 31;
    const int wid  = tid >> 5;
    const int wm   = wid & 3;
    const int wn   = wid >> 2;
    const int m0   = blockIdx.y * 128;
    const int n0   = blockIdx.x * 128;
    const uint32_t sbase = smem_u32(sm);
    const int lr = tid >> 3, lq = tid & 7;

    GDC_LAUNCH();

    auto issue_B = [&](int kc, int buf) {
        uint32_t sb = sbase + BF_A + buf * BF_B;
#pragma unroll
        for (int j = 0; j < 4; j++) {
            int r = lr + j * 32;
            cp16(sb + r * 128 + ((lq ^ (r & 7)) << 4),
                 wb + (size_t)(n0 + r) * 256 + kc * 64 + lq * 8);
        }
        cp_commit();
    };

    // ---- construct A tile pre-wait (depends only on kernel inputs) ----
    {
        int r = tid >> 1;
        int gr = m0 + r; if (gr > M - 1) gr = M - 1;
        int qb = (tid & 1) * 16;
        const float* xr = x + (size_t)gr * 128;
        const float* pr = pe + (size_t)gr * 98;
#pragma unroll
        for (int q = 0; q < 16; q++) {
            int gq = qb + q;
            int c0 = gq * 8;
            float v[8];
            if (c0 < 128) {
                float4 a = *reinterpret_cast<const float4*>(xr + c0);
                float4 b = *reinterpret_cast<const float4*>(xr + c0 + 4);
                v[0] = a.x; v[1] = a.y; v[2] = a.z; v[3] = a.w;
                v[4] = b.x; v[5] = b.y; v[6] = b.z; v[7] = b.w;
            } else {
#pragma unroll
                for (int p = 0; p < 4; p++) {
                    int pk = c0 + 2 * p - 128;
                    if (pk + 1 < 98) {
                        float2 t = *reinterpret_cast<const float2*>(pr + pk);
                        v[2 * p] = t.x; v[2 * p + 1] = t.y;
                    } else { v[2 * p] = 0.f; v[2 * p + 1] = 0.f; }
                }
            }
            uint4 val;
            __half2 h0 = __floats2half2_rn(v[0], v[1]);
            __half2 h1 = __floats2half2_rn(v[2], v[3]);
            __half2 h2 = __floats2half2_rn(v[4], v[5]);
            __half2 h3 = __floats2half2_rn(v[6], v[7]);
            val.x = *reinterpret_cast<uint32_t*>(&h0);
            val.y = *reinterpret_cast<uint32_t*>(&h1);
            val.z = *reinterpret_cast<uint32_t*>(&h2);
            val.w = *reinterpret_cast<uint32_t*>(&h3);
            uint32_t off = ((uint32_t)(gq >> 3) << 14) + r * 128
                         + (((gq & 7) ^ (r & 7)) << 4);
            *reinterpret_cast<uint4*>(sm + off) = val;
        }
    }

    GDC_WAIT();                 // wb ready (k_wtcat complete)
    issue_B(0, 0);

    float acc[2][8][4];
#pragma unroll
    for (int mi = 0; mi < 2; mi++)
#pragma unroll
        for (int ni = 0; ni < 8; ni++)
#pragma unroll
            for (int k = 0; k < 4; k++) acc[mi][ni][k] = 0.f;

    for (int kc = 0; kc < 4; kc++) {
        if (kc < 3) { issue_B(kc + 1, (kc + 1) & 1); cp_wait<1>(); }
        else        { cp_wait<0>(); }
        __syncthreads();
        uint32_t sa = sbase + ((uint32_t)kc << 14);
        uint32_t sb = sbase + BF_A + (kc & 1) * BF_B;
#pragma unroll
        for (int ks = 0; ks < 4; ks++) {
            uint32_t af[2][4];
#pragma unroll
            for (int mi = 0; mi < 2; mi++) {
                int row = wm * 32 + mi * 16 + (lane & 15);
                int c16 = (2 * ks + (lane >> 4)) ^ (row & 7);
                ldm_x4(af[mi], sa + row * 128 + (c16 << 4));
            }
            uint32_t bf[8][2];
#pragma unroll
            for (int np = 0; np < 4; np++) {
                int nrow = wn * 64 + np * 16 + ((lane >> 4) << 3) + (lane & 7);
                int c16 = (2 * ks + ((lane >> 3) & 1)) ^ (nrow & 7);
                uint32_t t4[4];
                ldm_x4(t4, sb + nrow * 128 + (c16 << 4));
                bf[np * 2][0] = t4[0]; bf[np * 2][1] = t4[1];
                bf[np * 2 + 1][0] = t4[2]; bf[np * 2 + 1][1] = t4[3];
            }
#pragma unroll
            for (int mi = 0; mi < 2; mi++)
#pragma unroll
                for (int ni = 0; ni < 8; ni++)
                    mma16816(acc[mi][ni], af[mi], bf[ni][0], bf[ni][1]);
        }
        __syncthreads();
    }

#pragma unroll
    for (int mi = 0; mi < 2; mi++) {
#pragma unroll
        for (int half = 0; half < 2; half++) {
            int r = m0 + wm * 32 + mi * 16 + (lane >> 2) + half * 8;
            if (r >= M) continue;
            size_t cbase = (size_t)r * 256 + n0 + wn * 64 + (lane & 3) * 2;
#pragma unroll
            for (int ni = 0; ni < 8; ni++) {
                __half2 hv = __floats2half2_rn(acc[mi][ni][half * 2],
                                               acc[mi][ni][half * 2 + 1]);
                *reinterpret_cast<__half2*>(xpe + cbase + ni * 8) = hv;
            }
        }
    }
}

// ================= merged CSR gather (both graphs, fp16 out) ==============
// PDL: CSR offsets/degree (preprocessing outputs, joined via event) load
// pre-wait; feature reads (predecessor GEMM output) post-wait.
__device__ __forceinline__ void st_half4(__half* p, float4 v) {
    __half2* hp = reinterpret_cast<__half2*>(p);
    hp[0] = __floats2half2_rn(v.x, v.y);
    hp[1] = __floats2half2_rn(v.z, v.w);
}

__global__ void k_gather2(const __half* __restrict__ src, int ld, int coff1,
                          const int* __restrict__ offs0, const int* __restrict__ offs1,
                          const Edge8* __restrict__ ent0, const Edge8* __restrict__ ent1,
                          const float* __restrict__ dis0, const float* __restrict__ dis1,
                          __half* __restrict__ o0, __half* __restrict__ o1, int n) {
    GDC_LAUNCH();
    int g = blockIdx.y;
    const int* offs = g ? offs1 : offs0;
    const Edge8* ent = g ? ent1 : ent0;
    const float* dis = g ? dis1 : dis0;
    __half* oh = g ? o1 : o0;
    int off = g ? coff1 : 0;

    int warp = (blockIdx.x * blockDim.x + threadIdx.x) >> 5;
    int lane = threadIdx.x & 31;
    if (warp >= n) { GDC_WAIT(); return; }
    float d = dis[warp];
    int b = offs[warp], e = offs[warp + 1];
    GDC_WAIT();                 // src ready (predecessor GEMM complete)
    float4 a1 = make_float4(0.f, 0.f, 0.f, 0.f);
    float4 a2 = make_float4(0.f, 0.f, 0.f, 0.f);
    int i = b;
    for (; i + 4 <= e; i += 4) {
        Edge8 r[4];
#pragma unroll
        for (int j = 0; j < 4; j++) r[j] = ent[i + j];
        float4 v[4];
#pragma unroll
        for (int j = 0; j < 4; j++)
            v[j] = ld_half4(src + (size_t)r[j].row * ld + off + lane * 4);
#pragma unroll
        for (int j = 0; j < 4; j++) {
            float c1 = __low2float(r[j].c) * d, c2 = __high2float(r[j].c);
            a1.x += c1 * v[j].x; a1.y += c1 * v[j].y; a1.z += c1 * v[j].z; a1.w += c1 * v[j].w;
            a2.x += c2 * v[j].x; a2.y += c2 * v[j].y; a2.z += c2 * v[j].z; a2.w += c2 * v[j].w;
        }
    }
    for (; i < e; i++) {
        Edge8 rec = ent[i];
        const float4 v = ld_half4(src + (size_t)rec.row * ld + off + lane * 4);
        float c1 = __low2float(rec.c) * d, c2 = __high2float(rec.c);
        a1.x += c1 * v.x; a1.y += c1 * v.y; a1.z += c1 * v.z; a1.w += c1 * v.w;
        a2.x += c2 * v.x; a2.y += c2 * v.y; a2.z += c2 * v.z; a2.w += c2 * v.w;
    }
    float sc = d * d;
    const float4 v = ld_half4(src + (size_t)warp * ld + off + lane * 4);
    a1.x += sc * v.x; a1.y += sc * v.y; a1.z += sc * v.z; a1.w += sc * v.w;
    a2.x += v.x;      a2.y += v.y;      a2.z += v.z;      a2.w += v.w;
    size_t base = (size_t)warp * 256 + lane * 4;
    st_half4(oh + base,       a1);
    st_half4(oh + base + 128, a2);
}

// ================= HMMA fp16 dual-source GEMM (stages D/F) ================
// PDL: B (weights from side stream) loads pre-wait; A (gather output) post-wait.
struct GArgs {
    const __half* A[2];
    const __half* B[2];
    void* C;
    int M, NC;
};

template <bool OUTH>
__global__ void __launch_bounds__(256, 2) k_gemm2(GArgs args) {
    constexpr int APL  = 16384;
    constexpr int ABUF = 2 * APL;
    constexpr int BPL  = 64 * 128;
    constexpr int BBUF = 2 * BPL;
    constexpr int BUF  = ABUF + BBUF;

    extern __shared__ char sm[];
    const int tid  = threadIdx.x;
    const int lane = tid & 31;
    const int wid  = tid >> 5;
    const int wm   = wid & 3;
    const int wn   = wid >> 2;
    const int m0   = blockIdx.y * 128;
    const int n0   = blockIdx.x * 64;
    const uint32_t sbase = smem_u32(sm);

    const int lr = tid >> 3, lq = tid & 7;

    GDC_LAUNCH();

    auto issue_A = [&](int kc, int buf) {
        uint32_t sb = sbase + buf * BUF;
#pragma unroll
        for (int s = 0; s < 2; s++) {
            const __half* A = args.A[s];
            uint32_t sa = sb + s * APL;
#pragma unroll
            for (int j = 0; j < 4; j++) {
                int r = lr + j * 32;
                int gr = m0 + r; if (gr > args.M - 1) gr = args.M - 1;
                cp16(sa + r * 128 + ((lq ^ (r & 7)) << 4),
                     A + (size_t)gr * 256 + kc * 64 + lq * 8);
            }
        }
        cp_commit();
    };
    auto issue_B = [&](int kc, int buf) {
        uint32_t sb = sbase + buf * BUF;
#pragma unroll
        for (int s = 0; s < 2; s++) {
            const __half* B = args.B[s];
            uint32_t sbB = sb + ABUF + s * BPL;
#pragma unroll
            for (int j = 0; j < 2; j++) {
                int r = lr + j * 32;
                cp16(sbB + r * 128 + ((lq ^ (r & 7)) << 4),
                     B + (size_t)(n0 + r) * 256 + kc * 64 + lq * 8);
            }
        }
        cp_commit();
    };

    float acc[2][2][4][4];
#pragma unroll
    for (int s = 0; s < 2; s++)
#pragma unroll
        for (int mi = 0; mi < 2; mi++)
#pragma unroll
            for (int ni = 0; ni < 4; ni++)
#pragma unroll
                for (int k = 0; k < 4; k++) acc[s][mi][ni][k] = 0.f;

    issue_B(0, 0);              // weights: safe pre-wait
    GDC_WAIT();                 // gather output ready
    issue_A(0, 0);

    for (int kc = 0; kc < 4; kc++) {
        if (kc < 3) {
            issue_B(kc + 1, (kc + 1) & 1);
            issue_A(kc + 1, (kc + 1) & 1);
            cp_wait<2>();
        } else {
            cp_wait<0>();
        }
        __syncthreads();
        uint32_t sb = sbase + (kc & 1) * BUF;
#pragma unroll
        for (int ks = 0; ks < 4; ks++) {
#pragma unroll
            for (int s = 0; s < 2; s++) {
                uint32_t af[2][4];
#pragma unroll
                for (int mi = 0; mi < 2; mi++) {
                    int row = wm * 32 + mi * 16 + (lane & 15);
                    int c16 = (2 * ks + (lane >> 4)) ^ (row & 7);
                    ldm_x4(af[mi], sb + s * APL + row * 128 + (c16 << 4));
                }
                uint32_t bf[4][2];
#pragma unroll
                for (int np = 0; np < 2; np++) {
                    int nrow = wn * 32 + np * 16 + ((lane >> 4) << 3) + (lane & 7);
                    int c16 = (2 * ks + ((lane >> 3) & 1)) ^ (nrow & 7);
                    uint32_t t4[4];
                    ldm_x4(t4, sb + ABUF + s * BPL + nrow * 128 + (c16 << 4));
                    bf[np * 2][0] = t4[0]; bf[np * 2][1] = t4[1];
                    bf[np * 2 + 1][0] = t4[2]; bf[np * 2 + 1][1] = t4[3];
                }
#pragma unroll
                for (int mi = 0; mi < 2; mi++)
#pragma unroll
                    for (int ni = 0; ni < 4; ni++)
                        mma16816(acc[s][mi][ni], af[mi], bf[ni][0], bf[ni][1]);
            }
        }
        __syncthreads();
    }

#pragma unroll
    for (int mi = 0; mi < 2; mi++) {
#pragma unroll
        for (int half = 0; half < 2; half++) {
            int r = m0 + wm * 32 + mi * 16 + (lane >> 2) + half * 8;
            if (r >= args.M) continue;
            size_t cbase = (size_t)r * args.NC + n0 + wn * 32 + (lane & 3) * 2;
#pragma unroll
            for (int ni = 0; ni < 4; ni++) {
                float v0 = 0.5f * (fmaxf(acc[0][mi][ni][half * 2], 0.f) +
                                   fmaxf(acc[1][mi][ni][half * 2], 0.f));
                float v1 = 0.5f * (fmaxf(acc[0][mi][ni][half * 2 + 1], 0.f) +
                                   fmaxf(acc[1][mi][ni][half * 2 + 1], 0.f));
                if (OUTH) {
                    __half2 hv = __floats2half2_rn(v0, v1);
                    *reinterpret_cast<__half2*>((__half*)args.C + cbase + ni * 8) = hv;
                } else {
                    float* cp = (float*)args.C + cbase + ni * 8;
                    cp[0] = v0; cp[1] = v1;
                }
            }
        }
    }
}

#define SMEM_DF (2 * (2 * 16384 + 2 * 64 * 128))       // 98304

// ================= host orchestration =================
extern "C" void kernel_launch(void* const* d_in, const int* in_sizes, int n_in,
                              void* d_out, int out_size) {
    const float* x   = (const float*)d_in[0];
    const float* pe  = (const float*)d_in[1];
    const int*   ei0 = (const int*)d_in[2];
    const float* ea0 = (const float*)d_in[3];
    const int*   ei1 = (const int*)d_in[4];
    const float* ea1 = (const float*)d_in[5];
    const float* nl1 = (const float*)d_in[6];
    const float* nl2 = (const float*)d_in[7];
    const float* lw[8] = { (const float*)d_in[8],  (const float*)d_in[9],
                           (const float*)d_in[10], (const float*)d_in[11],
                           (const float*)d_in[12], (const float*)d_in[13],
                           (const float*)d_in[14], (const float*)d_in[15] };
    float* out = (float*)d_out;

    int N = in_sizes[0] / 128;
    int E = in_sizes[3];

    __half *xpeh, *a0, *a1, *xmh, *wb, *ws;
    float *dis0, *dis1;
    int *cnt, *off0, *off1, *cur0, *cur1;
    Edge8 *ent0, *ent1;
    cudaGetSymbolAddress((void**)&xpeh, g_xpeh);
    cudaGetSymbolAddress((void**)&a0,  g_a0);
    cudaGetSymbolAddress((void**)&a1,  g_a1);
    cudaGetSymbolAddress((void**)&xmh, g_xmh);
    cudaGetSymbolAddress((void**)&wb,  g_wb);
    cudaGetSymbolAddress((void**)&ws,  g_ws);
    cudaGetSymbolAddress((void**)&cnt, g_cnt);
    cudaGetSymbolAddress((void**)&off0, g_off0);
    cudaGetSymbolAddress((void**)&off1, g_off1);
    cudaGetSymbolAddress((void**)&cur0, g_cur0);
    cudaGetSymbolAddress((void**)&cur1, g_cur1);
    cudaGetSymbolAddress((void**)&dis0, g_dis0);
    cudaGetSymbolAddress((void**)&dis1, g_dis1);
    cudaGetSymbolAddress((void**)&ent0, g_ent0);
    cudaGetSymbolAddress((void**)&ent1, g_ent1);
    int* cnt0 = cnt;
    int* cnt1 = cnt + MAXN;

    cudaFuncSetAttribute((const void*)k_gemmBF,
                         cudaFuncAttributeMaxDynamicSharedMemorySize, SMEM_BF);
    cudaFuncSetAttribute((const void*)k_gemm2<true>,
                         cudaFuncAttributeMaxDynamicSharedMemorySize, SMEM_DF);
    cudaFuncSetAttribute((const void*)k_gemm2<false>,
                         cudaFuncAttributeMaxDynamicSharedMemorySize, SMEM_DF);

    static cudaStream_t s1 = nullptr;
    static cudaEvent_t ev[2];
    if (s1 == nullptr) {
        cudaStreamCreateWithFlags(&s1, cudaStreamNonBlocking);
        for (int i = 0; i < 2; i++) cudaEventCreateWithFlags(&ev[i], cudaEventDisableTiming);
    }

    int eb = (E + 255) / 256;
    int mtiles = (N + 127) / 128;
    int gw = (N + 7) / 8;

    // PDL launcher (programmatic stream serialization on the dependent)
    auto launch_pdl = [](auto kern, dim3 grid, dim3 block, size_t smem, auto... args) {
        cudaLaunchConfig_t cfg = {};
        cfg.gridDim = grid; cfg.blockDim = block;
        cfg.dynamicSmemBytes = smem; cfg.stream = 0;
        cudaLaunchAttribute at[1];
        at[0].id = cudaLaunchAttributeProgrammaticStreamSerialization;
        at[0].val.programmaticStreamSerializationAllowed = 1;
        cfg.attrs = at; cfg.numAttrs = 1;
        cudaLaunchKernelEx(&cfg, kern, args...);
    };

    // ======== fork: preprocessing + ws prep on s1 ========
    cudaEventRecord(ev[0], 0);
    cudaStreamWaitEvent(s1, ev[0], 0);

    cudaMemsetAsync(cnt, 0, 2 * MAXN * sizeof(int), s1);
    k_count2<<<dim3(eb, 2), 256, 0, s1>>>(ei0 + E, ei1 + E, cnt0, cnt1, E);
    k_scan2<<<2, 1024, 0, s1>>>(cnt0, cnt1, off0, off1, cur0, cur1, dis0, dis1, N);
    k_fill2<<<dim3(eb, 2), 256, 0, s1>>>(ei0, ea0, ei1, ea1, dis0, dis1,
                                         cur0, cur1, ent0, ent1, E);
    k_wtstk4<<<dim3(128, 4), 256, 0, s1>>>(lw[0], lw[1], lw[2], lw[3],
                                           lw[4], lw[5], lw[6], lw[7], ws);
    cudaEventRecord(ev[1], s1);

    // main: wcat prep + fused stage B (PDL pair: wtcat -> gemmBF)
    k_wtcat<<<256, 256>>>(nl1, nl2, wb);
    launch_pdl(k_gemmBF, dim3(2, mtiles), dim3(256), (size_t)SMEM_BF,
               x, pe, (const __half*)wb, xpeh, N);
    cudaStreamWaitEvent(0, ev[1], 0);   // join preprocessing + ws

    // ======== stage C (PDL: overlaps gemmBF tail) ========
    launch_pdl(k_gather2, dim3(gw, 2), dim3(256), (size_t)0,
               (const __half*)xpeh, 256, 128,
               (const int*)off0, (const int*)off1,
               (const Edge8*)ent0, (const Edge8*)ent1,
               (const float*)dis0, (const float*)dis1, a0, a1, N);

    // ======== stage D (PDL: B-weight prologue overlaps gather tail) ========
    {
        GArgs a = {};
        a.A[0] = a0; a.A[1] = a1;
        a.B[0] = ws + 0 * 32768;
        a.B[1] = ws + 1 * 32768;
        a.C = xmh; a.M = N; a.NC = 128;
        launch_pdl(k_gemm2<true>, dim3(2, mtiles), dim3(256), (size_t)SMEM_DF, a);
    }

    // ======== stage E ========
    launch_pdl(k_gather2, dim3(gw, 2), dim3(256), (size_t)0,
               (const __half*)xmh, 128, 0,
               (const int*)off0, (const int*)off1,
               (const Edge8*)ent0, (const Edge8*)ent1,
               (const float*)dis0, (const float*)dis1, a0, a1, N);

    // ======== stage F ========
    {
        GArgs a = {};
        a.A[0] = a0; a.A[1] = a1;
        a.B[0] = ws + 2 * 32768;
        a.B[1] = ws + 3 * 32768;
        a.C = out; a.M = N; a.NC = 128;
        launch_pdl(k_gemm2<false>, dim3(2, mtiles), dim3(256), (size_t)SMEM_DF, a);
    }
}

// round 15
// speedup vs baseline: 1.0063x; 1.0063x over previous
#include <cuda_runtime.h>
#include <cuda_fp16.h>
#include <cstdint>

#define MAXN 50000
#define MAXE 800000

// ================= device scratch =================
struct __align__(8) Edge8 { int row; __half2 c; };   // c = (dis[row], c2)

__device__ __half g_xpeh[MAXN * 256];
__device__ __half g_a0  [MAXN * 256];
__device__ __half g_a1  [MAXN * 256];
__device__ __half g_xmh [MAXN * 128];
__device__ __half g_wb  [256 * 256];
__device__ __half g_ws  [4][128 * 256];
__device__ int   g_cnt [2 * MAXN];
__device__ int   g_off0[MAXN + 1];
__device__ int   g_off1[MAXN + 1];
__device__ int   g_cur0[MAXN];
__device__ int   g_cur1[MAXN];
__device__ float g_dis0[MAXN];
__device__ float g_dis1[MAXN];
__device__ Edge8 g_ent0[MAXE];
__device__ Edge8 g_ent1[MAXE];

// ================= batched graph preprocessing =================
__global__ void k_count2(const int* __restrict__ c0, const int* __restrict__ c1,
                         int* __restrict__ cnt0, int* __restrict__ cnt1, int e) {
    int i = blockIdx.x * blockDim.x + threadIdx.x;
    const int* col = blockIdx.y ? c1 : c0;
    int* cnt = blockIdx.y ? cnt1 : cnt0;
    if (i < e) atomicAdd(&cnt[col[i]], 1);
}
__global__ void k_scan2(const int* __restrict__ cnt0, const int* __restrict__ cnt1,
                        int* __restrict__ off0, int* __restrict__ off1,
                        int* __restrict__ cur0, int* __restrict__ cur1,
                        float* __restrict__ dis0, float* __restrict__ dis1, int n) {
    __shared__ int s[1024];
    const int* cnt = blockIdx.x ? cnt1 : cnt0;
    int* off = blockIdx.x ? off1 : off0;
    int* cur = blockIdx.x ? cur1 : cur0;
    float* dis = blockIdx.x ? dis1 : dis0;
    int t = threadIdx.x;
    int chunk = (n + 1023) >> 10;
    int b = t * chunk;
    int e = min(b + chunk, n);
    int sum = 0;
    for (int i = b; i < e; i++) sum += cnt[i];
    s[t] = sum;
    __syncthreads();
    for (int o = 1; o < 1024; o <<= 1) {
        int v = (t >= o) ? s[t - o] : 0;
        __syncthreads();
        s[t] += v;
        __syncthreads();
    }
    int base = s[t] - sum;
    for (int i = b; i < e; i++) {
        int c = cnt[i];
        off[i] = base; cur[i] = base; base += c;
        dis[i] = rsqrtf((float)(c + 1));
    }
    if (t == 1023) off[n] = s[1023];
}
__global__ void k_fill2(const int* __restrict__ ei0, const float* __restrict__ ea0,
                        const int* __restrict__ ei1, const float* __restrict__ ea1,
                        const float* __restrict__ dis0, const float* __restrict__ dis1,
                        int* __restrict__ cur0, int* __restrict__ cur1,
                        Edge8* __restrict__ ent0, Edge8* __restrict__ ent1, int e) {
    int i = blockIdx.x * blockDim.x + threadIdx.x;
    if (i >= e) return;
    const int* ei = blockIdx.y ? ei1 : ei0;
    const float* attr = blockIdx.y ? ea1 : ea0;
    const float* dis = blockIdx.y ? dis1 : dis0;
    int* cur = blockIdx.y ? cur1 : cur0;
    Edge8* ent = blockIdx.y ? ent1 : ent0;
    int r = ei[i], c = ei[e + i];
    float a = attr[i];
    float c2 = (a > 0.f) ? fminf(rsqrtf(a), 1.f) : 0.f;
    Edge8 rec;
    rec.row = r;
    rec.c = __floats2half2_rn(dis[r], c2);
    int p = atomicAdd(&cur[c], 1);
    ent[p] = rec;
}

// ================= weight prep ======================
__global__ void k_wtcat(const float* __restrict__ w1, const float* __restrict__ w2,
                        __half* __restrict__ w) {
    int idx = blockIdx.x * blockDim.x + threadIdx.x;
    if (idx >= 256 * 256) return;
    int n = idx >> 8, k = idx & 255;
    float v = 0.f;
    if (k < 226) v = (n < 128) ? w1[k * 128 + n] : w2[k * 128 + (n - 128)];
    w[idx] = __float2half_rn(v);
}
__global__ void k_wtstk4(const float* __restrict__ w10, const float* __restrict__ w20,
                         const float* __restrict__ w11, const float* __restrict__ w21,
                         const float* __restrict__ w12, const float* __restrict__ w22,
                         const float* __restrict__ w13, const float* __restrict__ w23,
                         __half* __restrict__ w) {
    int idx = blockIdx.x * blockDim.x + threadIdx.x;
    if (idx >= 128 * 256) return;
    int g = blockIdx.y;
    const float* w1 = (g == 0) ? w10 : (g == 1) ? w11 : (g == 2) ? w12 : w13;
    const float* w2 = (g == 0) ? w20 : (g == 1) ? w21 : (g == 2) ? w22 : w23;
    int n = idx >> 8, k = idx & 255;
    float v = (k < 128) ? w1[k * 128 + n] : w2[(k - 128) * 128 + n];
    w[g * 32768 + idx] = __float2half_rn(v);
}

// ================= common PTX helpers =========================
__device__ __forceinline__ uint32_t smem_u32(const void* p) {
    uint32_t a;
    asm("{ .reg .u64 t; cvta.to.shared.u64 t, %1; cvt.u32.u64 %0, t; }" : "=r"(a) : "l"(p));
    return a;
}
__device__ __forceinline__ void cp16(uint32_t dst, const void* src) {
    asm volatile("cp.async.cg.shared.global [%0], [%1], 16;" :: "r"(dst), "l"(src));
}
__device__ __forceinline__ void cp_commit() { asm volatile("cp.async.commit_group;"); }
template <int W> __device__ __forceinline__ void cp_wait() {
    asm volatile("cp.async.wait_group %0;" :: "n"(W));
}
__device__ __forceinline__ void ldm_x4(uint32_t* r, uint32_t addr) {
    asm volatile("ldmatrix.sync.aligned.m8n8.x4.shared.b16 {%0,%1,%2,%3}, [%4];"
                 : "=r"(r[0]), "=r"(r[1]), "=r"(r[2]), "=r"(r[3]) : "r"(addr));
}
__device__ __forceinline__ void mma16816(float* c, const uint32_t* a, uint32_t b0, uint32_t b1) {
    asm volatile(
        "mma.sync.aligned.m16n8k16.row.col.f32.f16.f16.f32 "
        "{%0,%1,%2,%3}, {%4,%5,%6,%7}, {%8,%9}, {%0,%1,%2,%3};"
        : "+f"(c[0]), "+f"(c[1]), "+f"(c[2]), "+f"(c[3])
        : "r"(a[0]), "r"(a[1]), "r"(a[2]), "r"(a[3]), "r"(b0), "r"(b1));
}
__device__ __forceinline__ float4 ld_half4(const __half* p) {
    uint2 raw = *reinterpret_cast<const uint2*>(p);
    __half2 h0 = *reinterpret_cast<const __half2*>(&raw.x);
    __half2 h1 = *reinterpret_cast<const __half2*>(&raw.y);
    float2 f0 = __half22float2(h0), f1 = __half22float2(h1);
    return make_float4(f0.x, f0.y, f1.x, f1.y);
}

// ================= stage B: fused A-construct + HMMA GEMM ==============
#define BF_A 65536
#define BF_B 16384
#define SMEM_BF (BF_A + 2 * BF_B)   // 98304

__global__ void __launch_bounds__(256, 2) k_gemmBF(
    const float* __restrict__ x, const float* __restrict__ pe,
    const __half* __restrict__ wb, __half* __restrict__ xpe, int M) {
    extern __shared__ char sm[];
    const int tid  = threadIdx.x;
    const int lane = tid & 31;
    const int wid  = tid >> 5;
    const int wm   = wid & 3;
    const int wn   = wid >> 2;
    const int m0   = blockIdx.y * 128;
    const int n0   = blockIdx.x * 128;
    const uint32_t sbase = smem_u32(sm);
    const int lr = tid >> 3, lq = tid & 7;

    auto issue_B = [&](int kc, int buf) {
        uint32_t sb = sbase + BF_A + buf * BF_B;
#pragma unroll
        for (int j = 0; j < 4; j++) {
            int r = lr + j * 32;
            cp16(sb + r * 128 + ((lq ^ (r & 7)) << 4),
                 wb + (size_t)(n0 + r) * 256 + kc * 64 + lq * 8);
        }
        cp_commit();
    };
    issue_B(0, 0);

    {
        int r = tid >> 1;
        int gr = m0 + r; if (gr > M - 1) gr = M - 1;
        int qb = (tid & 1) * 16;
        const float* xr = x + (size_t)gr * 128;
        const float* pr = pe + (size_t)gr * 98;
#pragma unroll
        for (int q = 0; q < 16; q++) {
            int gq = qb + q;
            int c0 = gq * 8;
            float v[8];
            if (c0 < 128) {
                float4 a = *reinterpret_cast<const float4*>(xr + c0);
                float4 b = *reinterpret_cast<const float4*>(xr + c0 + 4);
                v[0] = a.x; v[1] = a.y; v[2] = a.z; v[3] = a.w;
                v[4] = b.x; v[5] = b.y; v[6] = b.z; v[7] = b.w;
            } else {
#pragma unroll
                for (int p = 0; p < 4; p++) {
                    int pk = c0 + 2 * p - 128;
                    if (pk + 1 < 98) {
                        float2 t = *reinterpret_cast<const float2*>(pr + pk);
                        v[2 * p] = t.x; v[2 * p + 1] = t.y;
                    } else { v[2 * p] = 0.f; v[2 * p + 1] = 0.f; }
                }
            }
            uint4 val;
            __half2 h0 = __floats2half2_rn(v[0], v[1]);
            __half2 h1 = __floats2half2_rn(v[2], v[3]);
            __half2 h2 = __floats2half2_rn(v[4], v[5]);
            __half2 h3 = __floats2half2_rn(v[6], v[7]);
            val.x = *reinterpret_cast<uint32_t*>(&h0);
            val.y = *reinterpret_cast<uint32_t*>(&h1);
            val.z = *reinterpret_cast<uint32_t*>(&h2);
            val.w = *reinterpret_cast<uint32_t*>(&h3);
            uint32_t off = ((uint32_t)(gq >> 3) << 14) + r * 128
                         + (((gq & 7) ^ (r & 7)) << 4);
            *reinterpret_cast<uint4*>(sm + off) = val;
        }
    }

    float acc[2][8][4];
#pragma unroll
    for (int mi = 0; mi < 2; mi++)
#pragma unroll
        for (int ni = 0; ni < 8; ni++)
#pragma unroll
            for (int k = 0; k < 4; k++) acc[mi][ni][k] = 0.f;

    for (int kc = 0; kc < 4; kc++) {
        if (kc < 3) { issue_B(kc + 1, (kc + 1) & 1); cp_wait<1>(); }
        else        { cp_wait<0>(); }
        __syncthreads();
        uint32_t sa = sbase + ((uint32_t)kc << 14);
        uint32_t sb = sbase + BF_A + (kc & 1) * BF_B;
#pragma unroll
        for (int ks = 0; ks < 4; ks++) {
            uint32_t af[2][4];
#pragma unroll
            for (int mi = 0; mi < 2; mi++) {
                int row = wm * 32 + mi * 16 + (lane & 15);
                int c16 = (2 * ks + (lane >> 4)) ^ (row & 7);
                ldm_x4(af[mi], sa + row * 128 + (c16 << 4));
            }
            uint32_t bf[8][2];
#pragma unroll
            for (int np = 0; np < 4; np++) {
                int nrow = wn * 64 + np * 16 + ((lane >> 4) << 3) + (lane & 7);
                int c16 = (2 * ks + ((lane >> 3) & 1)) ^ (nrow & 7);
                uint32_t t4[4];
                ldm_x4(t4, sb + nrow * 128 + (c16 << 4));
                bf[np * 2][0] = t4[0]; bf[np * 2][1] = t4[1];
                bf[np * 2 + 1][0] = t4[2]; bf[np * 2 + 1][1] = t4[3];
            }
#pragma unroll
            for (int mi = 0; mi < 2; mi++)
#pragma unroll
                for (int ni = 0; ni < 8; ni++)
                    mma16816(acc[mi][ni], af[mi], bf[ni][0], bf[ni][1]);
        }
        __syncthreads();
    }

#pragma unroll
    for (int mi = 0; mi < 2; mi++) {
#pragma unroll
        for (int half = 0; half < 2; half++) {
            int r = m0 + wm * 32 + mi * 16 + (lane >> 2) + half * 8;
            if (r >= M) continue;
            size_t cbase = (size_t)r * 256 + n0 + wn * 64 + (lane & 3) * 2;
#pragma unroll
            for (int ni = 0; ni < 8; ni++) {
                __half2 hv = __floats2half2_rn(acc[mi][ni][half * 2],
                                               acc[mi][ni][half * 2 + 1]);
                *reinterpret_cast<__half2*>(xpe + cbase + ni * 8) = hv;
            }
        }
    }
}

// ================= merged CSR gather (both graphs, fp16 out) ==============
__device__ __forceinline__ void st_half4(__half* p, float4 v) {
    __half2* hp = reinterpret_cast<__half2*>(p);
    hp[0] = __floats2half2_rn(v.x, v.y);
    hp[1] = __floats2half2_rn(v.z, v.w);
}

__global__ void k_gather2(const __half* __restrict__ src, int ld, int coff1,
                          const int* __restrict__ offs0, const int* __restrict__ offs1,
                          const Edge8* __restrict__ ent0, const Edge8* __restrict__ ent1,
                          const float* __restrict__ dis0, const float* __restrict__ dis1,
                          __half* __restrict__ o0, __half* __restrict__ o1, int n) {
    int g = blockIdx.y;
    const int* offs = g ? offs1 : offs0;
    const Edge8* ent = g ? ent1 : ent0;
    const float* dis = g ? dis1 : dis0;
    __half* oh = g ? o1 : o0;
    int off = g ? coff1 : 0;

    int warp = (blockIdx.x * blockDim.x + threadIdx.x) >> 5;
    int lane = threadIdx.x & 31;
    if (warp >= n) return;
    float d = dis[warp];
    int b = offs[warp], e = offs[warp + 1];
    float4 a1 = make_float4(0.f, 0.f, 0.f, 0.f);
    float4 a2 = make_float4(0.f, 0.f, 0.f, 0.f);
    int i = b;
    for (; i + 4 <= e; i += 4) {
        Edge8 r[4];
#pragma unroll
        for (int j = 0; j < 4; j++) r[j] = ent[i + j];
        float4 v[4];
#pragma unroll
        for (int j = 0; j < 4; j++)
            v[j] = ld_half4(src + (size_t)r[j].row * ld + off + lane * 4);
#pragma unroll
        for (int j = 0; j < 4; j++) {
            float c1 = __low2float(r[j].c) * d, c2 = __high2float(r[j].c);
            a1.x += c1 * v[j].x; a1.y += c1 * v[j].y; a1.z += c1 * v[j].z; a1.w += c1 * v[j].w;
            a2.x += c2 * v[j].x; a2.y += c2 * v[j].y; a2.z += c2 * v[j].z; a2.w += c2 * v[j].w;
        }
    }
    for (; i < e; i++) {
        Edge8 rec = ent[i];
        const float4 v = ld_half4(src + (size_t)rec.row * ld + off + lane * 4);
        float c1 = __low2float(rec.c) * d, c2 = __high2float(rec.c);
        a1.x += c1 * v.x; a1.y += c1 * v.y; a1.z += c1 * v.z; a1.w += c1 * v.w;
        a2.x += c2 * v.x; a2.y += c2 * v.y; a2.z += c2 * v.z; a2.w += c2 * v.w;
    }
    float sc = d * d;
    const float4 v = ld_half4(src + (size_t)warp * ld + off + lane * 4);
    a1.x += sc * v.x; a1.y += sc * v.y; a1.z += sc * v.z; a1.w += sc * v.w;
    a2.x += v.x;      a2.y += v.y;      a2.z += v.z;      a2.w += v.w;
    size_t base = (size_t)warp * 256 + lane * 4;
    st_half4(oh + base,       a1);
    st_half4(oh + base + 128, a2);
}

// ================= HMMA fp16 dual-source GEMM (stages D/F) ================
struct GArgs {
    const __half* A[2];
    const __half* B[2];
    void* C;
    int M, NC;
};

template <bool OUTH>
__global__ void __launch_bounds__(256, 2) k_gemm2(GArgs args) {
    constexpr int APL  = 16384;
    constexpr int ABUF = 2 * APL;
    constexpr int BPL  = 64 * 128;
    constexpr int BBUF = 2 * BPL;
    constexpr int BUF  = ABUF + BBUF;

    extern __shared__ char sm[];
    const int tid  = threadIdx.x;
    const int lane = tid & 31;
    const int wid  = tid >> 5;
    const int wm   = wid & 3;
    const int wn   = wid >> 2;
    const int m0   = blockIdx.y * 128;
    const int n0   = blockIdx.x * 64;
    const uint32_t sbase = smem_u32(sm);

    const int lr = tid >> 3, lq = tid & 7;

    auto issue_load = [&](int kc, int buf) {
        uint32_t sb = sbase + buf * BUF;
#pragma unroll
        for (int s = 0; s < 2; s++) {
            const __half* A = args.A[s];
            uint32_t sa = sb + s * APL;
#pragma unroll
            for (int j = 0; j < 4; j++) {
                int r = lr + j * 32;
                int gr = m0 + r; if (gr > args.M - 1) gr = args.M - 1;
                cp16(sa + r * 128 + ((lq ^ (r & 7)) << 4),
                     A + (size_t)gr * 256 + kc * 64 + lq * 8);
            }
        }
#pragma unroll
        for (int s = 0; s < 2; s++) {
            const __half* B = args.B[s];
            uint32_t sbB = sb + ABUF + s * BPL;
#pragma unroll
            for (int j = 0; j < 2; j++) {
                int r = lr + j * 32;
                cp16(sbB + r * 128 + ((lq ^ (r & 7)) << 4),
                     B + (size_t)(n0 + r) * 256 + kc * 64 + lq * 8);
            }
        }
        cp_commit();
    };

    float acc[2][2][4][4];
#pragma unroll
    for (int s = 0; s < 2; s++)
#pragma unroll
        for (int mi = 0; mi < 2; mi++)
#pragma unroll
            for (int ni = 0; ni < 4; ni++)
#pragma unroll
                for (int k = 0; k < 4; k++) acc[s][mi][ni][k] = 0.f;

    issue_load(0, 0);
    for (int kc = 0; kc < 4; kc++) {
        if (kc < 3) { issue_load(kc + 1, (kc + 1) & 1); cp_wait<1>(); }
        else        { cp_wait<0>(); }
        __syncthreads();
        uint32_t sb = sbase + (kc & 1) * BUF;
#pragma unroll
        for (int ks = 0; ks < 4; ks++) {
#pragma unroll
            for (int s = 0; s < 2; s++) {
                uint32_t af[2][4];
#pragma unroll
                for (int mi = 0; mi < 2; mi++) {
                    int row = wm * 32 + mi * 16 + (lane & 15);
                    int c16 = (2 * ks + (lane >> 4)) ^ (row & 7);
                    ldm_x4(af[mi], sb + s * APL + row * 128 + (c16 << 4));
                }
                uint32_t bf[4][2];
#pragma unroll
                for (int np = 0; np < 2; np++) {
                    int nrow = wn * 32 + np * 16 + ((lane >> 4) << 3) + (lane & 7);
                    int c16 = (2 * ks + ((lane >> 3) & 1)) ^ (nrow & 7);
                    uint32_t t4[4];
                    ldm_x4(t4, sb + ABUF + s * BPL + nrow * 128 + (c16 << 4));
                    bf[np * 2][0] = t4[0]; bf[np * 2][1] = t4[1];
                    bf[np * 2 + 1][0] = t4[2]; bf[np * 2 + 1][1] = t4[3];
                }
#pragma unroll
                for (int mi = 0; mi < 2; mi++)
#pragma unroll
                    for (int ni = 0; ni < 4; ni++)
                        mma16816(acc[s][mi][ni], af[mi], bf[ni][0], bf[ni][1]);
            }
        }
        __syncthreads();
    }

#pragma unroll
    for (int mi = 0; mi < 2; mi++) {
#pragma unroll
        for (int half = 0; half < 2; half++) {
            int r = m0 + wm * 32 + mi * 16 + (lane >> 2) + half * 8;
            if (r >= args.M) continue;
            size_t cbase = (size_t)r * args.NC + n0 + wn * 32 + (lane & 3) * 2;
#pragma unroll
            for (int ni = 0; ni < 4; ni++) {
                float v0 = 0.5f * (fmaxf(acc[0][mi][ni][half * 2], 0.f) +
                                   fmaxf(acc[1][mi][ni][half * 2], 0.f));
                float v1 = 0.5f * (fmaxf(acc[0][mi][ni][half * 2 + 1], 0.f) +
                                   fmaxf(acc[1][mi][ni][half * 2 + 1], 0.f));
                if (OUTH) {
                    __half2 hv = __floats2half2_rn(v0, v1);
                    *reinterpret_cast<__half2*>((__half*)args.C + cbase + ni * 8) = hv;
                } else {
                    float* cp = (float*)args.C + cbase + ni * 8;
                    cp[0] = v0; cp[1] = v1;
                }
            }
        }
    }
}

#define SMEM_DF (2 * (2 * 16384 + 2 * 64 * 128))       // 98304

// ================= host orchestration =================
extern "C" void kernel_launch(void* const* d_in, const int* in_sizes, int n_in,
                              void* d_out, int out_size) {
    const float* x   = (const float*)d_in[0];
    const float* pe  = (const float*)d_in[1];
    const int*   ei0 = (const int*)d_in[2];
    const float* ea0 = (const float*)d_in[3];
    const int*   ei1 = (const int*)d_in[4];
    const float* ea1 = (const float*)d_in[5];
    const float* nl1 = (const float*)d_in[6];
    const float* nl2 = (const float*)d_in[7];
    const float* lw[8] = { (const float*)d_in[8],  (const float*)d_in[9],
                           (const float*)d_in[10], (const float*)d_in[11],
                           (const float*)d_in[12], (const float*)d_in[13],
                           (const float*)d_in[14], (const float*)d_in[15] };
    float* out = (float*)d_out;

    int N = in_sizes[0] / 128;
    int E = in_sizes[3];

    __half *xpeh, *a0, *a1, *xmh, *wb, *ws;
    float *dis0, *dis1;
    int *cnt, *off0, *off1, *cur0, *cur1;
    Edge8 *ent0, *ent1;
    cudaGetSymbolAddress((void**)&xpeh, g_xpeh);
    cudaGetSymbolAddress((void**)&a0,  g_a0);
    cudaGetSymbolAddress((void**)&a1,  g_a1);
    cudaGetSymbolAddress((void**)&xmh, g_xmh);
    cudaGetSymbolAddress((void**)&wb,  g_wb);
    cudaGetSymbolAddress((void**)&ws,  g_ws);
    cudaGetSymbolAddress((void**)&cnt, g_cnt);
    cudaGetSymbolAddress((void**)&off0, g_off0);
    cudaGetSymbolAddress((void**)&off1, g_off1);
    cudaGetSymbolAddress((void**)&cur0, g_cur0);
    cudaGetSymbolAddress((void**)&cur1, g_cur1);
    cudaGetSymbolAddress((void**)&dis0, g_dis0);
    cudaGetSymbolAddress((void**)&dis1, g_dis1);
    cudaGetSymbolAddress((void**)&ent0, g_ent0);
    cudaGetSymbolAddress((void**)&ent1, g_ent1);
    int* cnt0 = cnt;
    int* cnt1 = cnt + MAXN;

    cudaFuncSetAttribute((const void*)k_gemmBF,
                         cudaFuncAttributeMaxDynamicSharedMemorySize, SMEM_BF);
    cudaFuncSetAttribute((const void*)k_gemm2<true>,
                         cudaFuncAttributeMaxDynamicSharedMemorySize, SMEM_DF);
    cudaFuncSetAttribute((const void*)k_gemm2<false>,
                         cudaFuncAttributeMaxDynamicSharedMemorySize, SMEM_DF);

    static cudaStream_t s1 = nullptr;
    static cudaEvent_t ev[3];
    if (s1 == nullptr) {
        cudaStreamCreateWithFlags(&s1, cudaStreamNonBlocking);
        for (int i = 0; i < 3; i++) cudaEventCreateWithFlags(&ev[i], cudaEventDisableTiming);
    }

    int eb = (E + 255) / 256;
    int mtiles = (N + 127) / 128;
    int gw = (N + 7) / 8;

    // ======== fork: preprocessing (gates C) then ws prep (gates D) on s1 ====
    cudaEventRecord(ev[0], 0);
    cudaStreamWaitEvent(s1, ev[0], 0);

    cudaMemsetAsync(cnt, 0, 2 * MAXN * sizeof(int), s1);
    k_count2<<<dim3(eb, 2), 256, 0, s1>>>(ei0 + E, ei1 + E, cnt0, cnt1, E);
    k_scan2<<<2, 1024, 0, s1>>>(cnt0, cnt1, off0, off1, cur0, cur1, dis0, dis1, N);
    k_fill2<<<dim3(eb, 2), 256, 0, s1>>>(ei0, ea0, ei1, ea1, dis0, dis1,
                                         cur0, cur1, ent0, ent1, E);
    cudaEventRecord(ev[1], s1);          // CSR ready -> gates stage C
    k_wtstk4<<<dim3(128, 4), 256, 0, s1>>>(lw[0], lw[1], lw[2], lw[3],
                                           lw[4], lw[5], lw[6], lw[7], ws);
    cudaEventRecord(ev[2], s1);          // ws ready -> gates stage D

    // main: wcat prep + fused stage B
    k_wtcat<<<256, 256>>>(nl1, nl2, wb);
    k_gemmBF<<<dim3(2, mtiles), 256, SMEM_BF>>>(x, pe, wb, xpeh, N);
    cudaStreamWaitEvent(0, ev[1], 0);    // join CSR only

    // ======== stage C: both graphs in one launch ========
    k_gather2<<<dim3(gw, 2), 256>>>(xpeh, 256, 128, off0, off1, ent0, ent1,
                                    dis0, dis1, a0, a1, N);
    cudaStreamWaitEvent(0, ev[2], 0);    // join ws before D

    // ======== stage D (fused dual-source GEMM, fp16 xm output) ========
    {
        GArgs a = {};
        a.A[0] = a0; a.A[1] = a1;
        a.B[0] = ws + 0 * 32768;
        a.B[1] = ws + 1 * 32768;
        a.C = xmh; a.M = N; a.NC = 128;
        k_gemm2<true><<<dim3(2, mtiles), 256, SMEM_DF>>>(a);
    }

    // ======== stage E ========
    k_gather2<<<dim3(gw, 2), 256>>>(xmh, 128, 0, off0, off1, ent0, ent1,
                                    dis0, dis1, a0, a1, N);

    // ======== stage F (fused dual-source GEMM, fp32 out) ========
    {
        GArgs a = {};
        a.A[0] = a0; a.A[1] = a1;
        a.B[0] = ws + 2 * 32768;
        a.B[1] = ws + 3 * 32768;
        a.C = out; a.M = N; a.NC = 128;
        k_gemm2<false><<<dim3(2, mtiles), 256, SMEM_DF>>>(a);
    }
}

// round 16
// speedup vs baseline: 1.1891x; 1.1816x over previous
#include <cuda_runtime.h>
#include <cuda_fp16.h>
#include <cstdint>

#define MAXN 50000
#define MAXE 800000

// ================= device scratch =================
struct __align__(8) Edge8 { int row; __half2 c; };   // c = (dis[row], c2)

__device__ __half g_xpeh[MAXN * 256];
__device__ __half g_a0  [MAXN * 256];
__device__ __half g_a1  [MAXN * 256];
__device__ __half g_xmh [MAXN * 128];
__device__ __half g_wb  [256 * 256];
__device__ __half g_ws  [4][128 * 256];
__device__ int   g_cnt [2 * MAXN];
__device__ int   g_off0[MAXN + 1];
__device__ int   g_off1[MAXN + 1];
__device__ int   g_cur0[MAXN];
__device__ int   g_cur1[MAXN];
__device__ float g_dis0[MAXN];
__device__ float g_dis1[MAXN];
__device__ Edge8 g_ent0[MAXE];
__device__ Edge8 g_ent1[MAXE];

// ================= batched graph preprocessing =================
__global__ void k_count2(const int* __restrict__ c0, const int* __restrict__ c1,
                         int* __restrict__ cnt0, int* __restrict__ cnt1, int e) {
    int i = blockIdx.x * blockDim.x + threadIdx.x;
    const int* col = blockIdx.y ? c1 : c0;
    int* cnt = blockIdx.y ? cnt1 : cnt0;
    if (i < e) atomicAdd(&cnt[col[i]], 1);
}
__global__ void k_scan2(const int* __restrict__ cnt0, const int* __restrict__ cnt1,
                        int* __restrict__ off0, int* __restrict__ off1,
                        int* __restrict__ cur0, int* __restrict__ cur1,
                        float* __restrict__ dis0, float* __restrict__ dis1, int n) {
    __shared__ int s[1024];
    const int* cnt = blockIdx.x ? cnt1 : cnt0;
    int* off = blockIdx.x ? off1 : off0;
    int* cur = blockIdx.x ? cur1 : cur0;
    float* dis = blockIdx.x ? dis1 : dis0;
    int t = threadIdx.x;
    int chunk = (n + 1023) >> 10;
    int b = t * chunk;
    int e = min(b + chunk, n);
    int sum = 0;
    for (int i = b; i < e; i++) sum += cnt[i];
    s[t] = sum;
    __syncthreads();
    for (int o = 1; o < 1024; o <<= 1) {
        int v = (t >= o) ? s[t - o] : 0;
        __syncthreads();
        s[t] += v;
        __syncthreads();
    }
    int base = s[t] - sum;
    for (int i = b; i < e; i++) {
        int c = cnt[i];
        off[i] = base; cur[i] = base; base += c;
        dis[i] = rsqrtf((float)(c + 1));
    }
    if (t == 1023) off[n] = s[1023];
}
__global__ void k_fill2(const int* __restrict__ ei0, const float* __restrict__ ea0,
                        const int* __restrict__ ei1, const float* __restrict__ ea1,
                        const float* __restrict__ dis0, const float* __restrict__ dis1,
                        int* __restrict__ cur0, int* __restrict__ cur1,
                        Edge8* __restrict__ ent0, Edge8* __restrict__ ent1, int e) {
    int i = blockIdx.x * blockDim.x + threadIdx.x;
    if (i >= e) return;
    const int* ei = blockIdx.y ? ei1 : ei0;
    const float* attr = blockIdx.y ? ea1 : ea0;
    const float* dis = blockIdx.y ? dis1 : dis0;
    int* cur = blockIdx.y ? cur1 : cur0;
    Edge8* ent = blockIdx.y ? ent1 : ent0;
    int r = ei[i], c = ei[e + i];
    float a = attr[i];
    float c2 = (a > 0.f) ? fminf(rsqrtf(a), 1.f) : 0.f;
    Edge8 rec;
    rec.row = r;
    rec.c = __floats2half2_rn(dis[r], c2);
    int p = atomicAdd(&cur[c], 1);
    ent[p] = rec;
}

// ================= weight prep ======================
__global__ void k_wtcat(const float* __restrict__ w1, const float* __restrict__ w2,
                        __half* __restrict__ w) {
    int idx = blockIdx.x * blockDim.x + threadIdx.x;
    if (idx >= 256 * 256) return;
    int n = idx >> 8, k = idx & 255;
    float v = 0.f;
    if (k < 226) v = (n < 128) ? w1[k * 128 + n] : w2[k * 128 + (n - 128)];
    w[idx] = __float2half_rn(v);
}
__global__ void k_wtstk4(const float* __restrict__ w10, const float* __restrict__ w20,
                         const float* __restrict__ w11, const float* __restrict__ w21,
                         const float* __restrict__ w12, const float* __restrict__ w22,
                         const float* __restrict__ w13, const float* __restrict__ w23,
                         __half* __restrict__ w) {
    int idx = blockIdx.x * blockDim.x + threadIdx.x;
    if (idx >= 128 * 256) return;
    int g = blockIdx.y;
    const float* w1 = (g == 0) ? w10 : (g == 1) ? w11 : (g == 2) ? w12 : w13;
    const float* w2 = (g == 0) ? w20 : (g == 1) ? w21 : (g == 2) ? w22 : w23;
    int n = idx >> 8, k = idx & 255;
    float v = (k < 128) ? w1[k * 128 + n] : w2[(k - 128) * 128 + n];
    w[g * 32768 + idx] = __float2half_rn(v);
}

// ================= common PTX helpers =========================
__device__ __forceinline__ uint32_t smem_u32(const void* p) {
    uint32_t a;
    asm("{ .reg .u64 t; cvta.to.shared.u64 t, %1; cvt.u32.u64 %0, t; }" : "=r"(a) : "l"(p));
    return a;
}
__device__ __forceinline__ void cp16(uint32_t dst, const void* src) {
    asm volatile("cp.async.cg.shared.global [%0], [%1], 16;" :: "r"(dst), "l"(src));
}
__device__ __forceinline__ void cp_commit() { asm volatile("cp.async.commit_group;"); }
template <int W> __device__ __forceinline__ void cp_wait() {
    asm volatile("cp.async.wait_group %0;" :: "n"(W));
}
__device__ __forceinline__ void ldm_x4(uint32_t* r, uint32_t addr) {
    asm volatile("ldmatrix.sync.aligned.m8n8.x4.shared.b16 {%0,%1,%2,%3}, [%4];"
                 : "=r"(r[0]), "=r"(r[1]), "=r"(r[2]), "=r"(r[3]) : "r"(addr));
}
__device__ __forceinline__ void mma16816(float* c, const uint32_t* a, uint32_t b0, uint32_t b1) {
    asm volatile(
        "mma.sync.aligned.m16n8k16.row.col.f32.f16.f16.f32 "
        "{%0,%1,%2,%3}, {%4,%5,%6,%7}, {%8,%9}, {%0,%1,%2,%3};"
        : "+f"(c[0]), "+f"(c[1]), "+f"(c[2]), "+f"(c[3])
        : "r"(a[0]), "r"(a[1]), "r"(a[2]), "r"(a[3]), "r"(b0), "r"(b1));
}
__device__ __forceinline__ float4 ld_half4(const __half* p) {
    uint2 raw = *reinterpret_cast<const uint2*>(p);
    __half2 h0 = *reinterpret_cast<const __half2*>(&raw.x);
    __half2 h1 = *reinterpret_cast<const __half2*>(&raw.y);
    float2 f0 = __half22float2(h0), f1 = __half22float2(h1);
    return make_float4(f0.x, f0.y, f1.x, f1.y);
}

// ================= stage B: fused A-construct + HMMA GEMM ==============
#define BF_A 65536
#define BF_B 16384
#define SMEM_BF (BF_A + 2 * BF_B)   // 98304

__global__ void __launch_bounds__(256, 2) k_gemmBF(
    const float* __restrict__ x, const float* __restrict__ pe,
    const __half* __restrict__ wb, __half* __restrict__ xpe, int M) {
    extern __shared__ char sm[];
    const int tid  = threadIdx.x;
    const int lane = tid & 31;
    const int wid  = tid >> 5;
    const int wm   = wid & 3;
    const int wn   = wid >> 2;
    const int m0   = blockIdx.y * 128;
    const int n0   = blockIdx.x * 128;
    const uint32_t sbase = smem_u32(sm);
    const int lr = tid >> 3, lq = tid & 7;

    auto issue_B = [&](int kc, int buf) {
        uint32_t sb = sbase + BF_A + buf * BF_B;
#pragma unroll
        for (int j = 0; j < 4; j++) {
            int r = lr + j * 32;
            cp16(sb + r * 128 + ((lq ^ (r & 7)) << 4),
                 wb + (size_t)(n0 + r) * 256 + kc * 64 + lq * 8);
        }
        cp_commit();
    };
    issue_B(0, 0);

    {
        int r = tid >> 1;
        int gr = m0 + r; if (gr > M - 1) gr = M - 1;
        int qb = (tid & 1) * 16;
        const float* xr = x + (size_t)gr * 128;
        const float* pr = pe + (size_t)gr * 98;
#pragma unroll
        for (int q = 0; q < 16; q++) {
            int gq = qb + q;
            int c0 = gq * 8;
            float v[8];
            if (c0 < 128) {
                float4 a = *reinterpret_cast<const float4*>(xr + c0);
                float4 b = *reinterpret_cast<const float4*>(xr + c0 + 4);
                v[0] = a.x; v[1] = a.y; v[2] = a.z; v[3] = a.w;
                v[4] = b.x; v[5] = b.y; v[6] = b.z; v[7] = b.w;
            } else {
#pragma unroll
                for (int p = 0; p < 4; p++) {
                    int pk = c0 + 2 * p - 128;
                    if (pk + 1 < 98) {
                        float2 t = *reinterpret_cast<const float2*>(pr + pk);
                        v[2 * p] = t.x; v[2 * p + 1] = t.y;
                    } else { v[2 * p] = 0.f; v[2 * p + 1] = 0.f; }
                }
            }
            uint4 val;
            __half2 h0 = __floats2half2_rn(v[0], v[1]);
            __half2 h1 = __floats2half2_rn(v[2], v[3]);
            __half2 h2 = __floats2half2_rn(v[4], v[5]);
            __half2 h3 = __floats2half2_rn(v[6], v[7]);
            val.x = *reinterpret_cast<uint32_t*>(&h0);
            val.y = *reinterpret_cast<uint32_t*>(&h1);
            val.z = *reinterpret_cast<uint32_t*>(&h2);
            val.w = *reinterpret_cast<uint32_t*>(&h3);
            uint32_t off = ((uint32_t)(gq >> 3) << 14) + r * 128
                         + (((gq & 7) ^ (r & 7)) << 4);
            *reinterpret_cast<uint4*>(sm + off) = val;
        }
    }

    float acc[2][8][4];
#pragma unroll
    for (int mi = 0; mi < 2; mi++)
#pragma unroll
        for (int ni = 0; ni < 8; ni++)
#pragma unroll
            for (int k = 0; k < 4; k++) acc[mi][ni][k] = 0.f;

    for (int kc = 0; kc < 4; kc++) {
        if (kc < 3) { issue_B(kc + 1, (kc + 1) & 1); cp_wait<1>(); }
        else        { cp_wait<0>(); }
        __syncthreads();
        uint32_t sa = sbase + ((uint32_t)kc << 14);
        uint32_t sb = sbase + BF_A + (kc & 1) * BF_B;
#pragma unroll
        for (int ks = 0; ks < 4; ks++) {
            uint32_t af[2][4];
#pragma unroll
            for (int mi = 0; mi < 2; mi++) {
                int row = wm * 32 + mi * 16 + (lane & 15);
                int c16 = (2 * ks + (lane >> 4)) ^ (row & 7);
                ldm_x4(af[mi], sa + row * 128 + (c16 << 4));
            }
            uint32_t bf[8][2];
#pragma unroll
            for (int np = 0; np < 4; np++) {
                int nrow = wn * 64 + np * 16 + ((lane >> 4) << 3) + (lane & 7);
                int c16 = (2 * ks + ((lane >> 3) & 1)) ^ (nrow & 7);
                uint32_t t4[4];
                ldm_x4(t4, sb + nrow * 128 + (c16 << 4));
                bf[np * 2][0] = t4[0]; bf[np * 2][1] = t4[1];
                bf[np * 2 + 1][0] = t4[2]; bf[np * 2 + 1][1] = t4[3];
            }
#pragma unroll
            for (int mi = 0; mi < 2; mi++)
#pragma unroll
                for (int ni = 0; ni < 8; ni++)
                    mma16816(acc[mi][ni], af[mi], bf[ni][0], bf[ni][1]);
        }
        __syncthreads();
    }

#pragma unroll
    for (int mi = 0; mi < 2; mi++) {
#pragma unroll
        for (int half = 0; half < 2; half++) {
            int r = m0 + wm * 32 + mi * 16 + (lane >> 2) + half * 8;
            if (r >= M) continue;
            size_t cbase = (size_t)r * 256 + n0 + wn * 64 + (lane & 3) * 2;
#pragma unroll
            for (int ni = 0; ni < 8; ni++) {
                __half2 hv = __floats2half2_rn(acc[mi][ni][half * 2],
                                               acc[mi][ni][half * 2 + 1]);
                *reinterpret_cast<__half2*>(xpe + cbase + ni * 8) = hv;
            }
        }
    }
}

// ================= merged CSR gather (both graphs, fp16 out) ==============
__device__ __forceinline__ void st_half4(__half* p, float4 v) {
    __half2* hp = reinterpret_cast<__half2*>(p);
    hp[0] = __floats2half2_rn(v.x, v.y);
    hp[1] = __floats2half2_rn(v.z, v.w);
}

__global__ void k_gather2(const __half* __restrict__ src, int ld, int coff1,
                          const int* __restrict__ offs0, const int* __restrict__ offs1,
                          const Edge8* __restrict__ ent0, const Edge8* __restrict__ ent1,
                          const float* __restrict__ dis0, const float* __restrict__ dis1,
                          __half* __restrict__ o0, __half* __restrict__ o1, int n) {
    int g = blockIdx.y;
    const int* offs = g ? offs1 : offs0;
    const Edge8* ent = g ? ent1 : ent0;
    const float* dis = g ? dis1 : dis0;
    __half* oh = g ? o1 : o0;
    int off = g ? coff1 : 0;

    int warp = (blockIdx.x * blockDim.x + threadIdx.x) >> 5;
    int lane = threadIdx.x & 31;
    if (warp >= n) return;
    float d = dis[warp];
    int b = offs[warp], e = offs[warp + 1];
    float4 a1 = make_float4(0.f, 0.f, 0.f, 0.f);
    float4 a2 = make_float4(0.f, 0.f, 0.f, 0.f);
    int i = b;
    for (; i + 4 <= e; i += 4) {
        Edge8 r[4];
#pragma unroll
        for (int j = 0; j < 4; j++) r[j] = ent[i + j];
        float4 v[4];
#pragma unroll
        for (int j = 0; j < 4; j++)
            v[j] = ld_half4(src + (size_t)r[j].row * ld + off + lane * 4);
#pragma unroll
        for (int j = 0; j < 4; j++) {
            float c1 = __low2float(r[j].c) * d, c2 = __high2float(r[j].c);
            a1.x += c1 * v[j].x; a1.y += c1 * v[j].y; a1.z += c1 * v[j].z; a1.w += c1 * v[j].w;
            a2.x += c2 * v[j].x; a2.y += c2 * v[j].y; a2.z += c2 * v[j].z; a2.w += c2 * v[j].w;
        }
    }
    for (; i < e; i++) {
        Edge8 rec = ent[i];
        const float4 v = ld_half4(src + (size_t)rec.row * ld + off + lane * 4);
        float c1 = __low2float(rec.c) * d, c2 = __high2float(rec.c);
        a1.x += c1 * v.x; a1.y += c1 * v.y; a1.z += c1 * v.z; a1.w += c1 * v.w;
        a2.x += c2 * v.x; a2.y += c2 * v.y; a2.z += c2 * v.z; a2.w += c2 * v.w;
    }
    float sc = d * d;
    const float4 v = ld_half4(src + (size_t)warp * ld + off + lane * 4);
    a1.x += sc * v.x; a1.y += sc * v.y; a1.z += sc * v.z; a1.w += sc * v.w;
    a2.x += v.x;      a2.y += v.y;      a2.z += v.z;      a2.w += v.w;
    size_t base = (size_t)warp * 256 + lane * 4;
    st_half4(oh + base,       a1);
    st_half4(oh + base + 128, a2);
}

// ================= HMMA fp16 dual-source GEMM (stages D/F) ================
struct GArgs {
    const __half* A[2];
    const __half* B[2];
    void* C;
    int M, NC;
};

template <bool OUTH>
__global__ void __launch_bounds__(256, 2) k_gemm2(GArgs args) {
    constexpr int APL  = 16384;
    constexpr int ABUF = 2 * APL;
    constexpr int BPL  = 64 * 128;
    constexpr int BBUF = 2 * BPL;
    constexpr int BUF  = ABUF + BBUF;

    extern __shared__ char sm[];
    const int tid  = threadIdx.x;
    const int lane = tid & 31;
    const int wid  = tid >> 5;
    const int wm   = wid & 3;
    const int wn   = wid >> 2;
    const int m0   = blockIdx.y * 128;
    const int n0   = blockIdx.x * 64;
    const uint32_t sbase = smem_u32(sm);

    const int lr = tid >> 3, lq = tid & 7;

    auto issue_load = [&](int kc, int buf) {
        uint32_t sb = sbase + buf * BUF;
#pragma unroll
        for (int s = 0; s < 2; s++) {
            const __half* A = args.A[s];
            uint32_t sa = sb + s * APL;
#pragma unroll
            for (int j = 0; j < 4; j++) {
                int r = lr + j * 32;
                int gr = m0 + r; if (gr > args.M - 1) gr = args.M - 1;
                cp16(sa + r * 128 + ((lq ^ (r & 7)) << 4),
                     A + (size_t)gr * 256 + kc * 64 + lq * 8);
            }
        }
#pragma unroll
        for (int s = 0; s < 2; s++) {
            const __half* B = args.B[s];
            uint32_t sbB = sb + ABUF + s * BPL;
#pragma unroll
            for (int j = 0; j < 2; j++) {
                int r = lr + j * 32;
                cp16(sbB + r * 128 + ((lq ^ (r & 7)) << 4),
                     B + (size_t)(n0 + r) * 256 + kc * 64 + lq * 8);
            }
        }
        cp_commit();
    };

    float acc[2][2][4][4];
#pragma unroll
    for (int s = 0; s < 2; s++)
#pragma unroll
        for (int mi = 0; mi < 2; mi++)
#pragma unroll
            for (int ni = 0; ni < 4; ni++)
#pragma unroll
                for (int k = 0; k < 4; k++) acc[s][mi][ni][k] = 0.f;

    issue_load(0, 0);
    for (int kc = 0; kc < 4; kc++) {
        if (kc < 3) { issue_load(kc + 1, (kc + 1) & 1); cp_wait<1>(); }
        else        { cp_wait<0>(); }
        __syncthreads();
        uint32_t sb = sbase + (kc & 1) * BUF;
#pragma unroll
        for (int ks = 0; ks < 4; ks++) {
#pragma unroll
            for (int s = 0; s < 2; s++) {
                uint32_t af[2][4];
#pragma unroll
                for (int mi = 0; mi < 2; mi++) {
                    int row = wm * 32 + mi * 16 + (lane & 15);
                    int c16 = (2 * ks + (lane >> 4)) ^ (row & 7);
                    ldm_x4(af[mi], sb + s * APL + row * 128 + (c16 << 4));
                }
                uint32_t bf[4][2];
#pragma unroll
                for (int np = 0; np < 2; np++) {
                    int nrow = wn * 32 + np * 16 + ((lane >> 4) << 3) + (lane & 7);
                    int c16 = (2 * ks + ((lane >> 3) & 1)) ^ (nrow & 7);
                    uint32_t t4[4];
                    ldm_x4(t4, sb + ABUF + s * BPL + nrow * 128 + (c16 << 4));
                    bf[np * 2][0] = t4[0]; bf[np * 2][1] = t4[1];
                    bf[np * 2 + 1][0] = t4[2]; bf[np * 2 + 1][1] = t4[3];
                }
#pragma unroll
                for (int mi = 0; mi < 2; mi++)
#pragma unroll
                    for (int ni = 0; ni < 4; ni++)
                        mma16816(acc[s][mi][ni], af[mi], bf[ni][0], bf[ni][1]);
            }
        }
        __syncthreads();
    }

#pragma unroll
    for (int mi = 0; mi < 2; mi++) {
#pragma unroll
        for (int half = 0; half < 2; half++) {
            int r = m0 + wm * 32 + mi * 16 + (lane >> 2) + half * 8;
            if (r >= args.M) continue;
            size_t cbase = (size_t)r * args.NC + n0 + wn * 32 + (lane & 3) * 2;
#pragma unroll
            for (int ni = 0; ni < 4; ni++) {
                float v0 = 0.5f * (fmaxf(acc[0][mi][ni][half * 2], 0.f) +
                                   fmaxf(acc[1][mi][ni][half * 2], 0.f));
                float v1 = 0.5f * (fmaxf(acc[0][mi][ni][half * 2 + 1], 0.f) +
                                   fmaxf(acc[1][mi][ni][half * 2 + 1], 0.f));
                if (OUTH) {
                    __half2 hv = __floats2half2_rn(v0, v1);
                    *reinterpret_cast<__half2*>((__half*)args.C + cbase + ni * 8) = hv;
                } else {
                    float* cp = (float*)args.C + cbase + ni * 8;
                    cp[0] = v0; cp[1] = v1;
                }
            }
        }
    }
}

#define SMEM_DF (2 * (2 * 16384 + 2 * 64 * 128))       // 98304

// ================= host orchestration =================
extern "C" void kernel_launch(void* const* d_in, const int* in_sizes, int n_in,
                              void* d_out, int out_size) {
    const float* x   = (const float*)d_in[0];
    const float* pe  = (const float*)d_in[1];
    const int*   ei0 = (const int*)d_in[2];
    const float* ea0 = (const float*)d_in[3];
    const int*   ei1 = (const int*)d_in[4];
    const float* ea1 = (const float*)d_in[5];
    const float* nl1 = (const float*)d_in[6];
    const float* nl2 = (const float*)d_in[7];
    const float* lw[8] = { (const float*)d_in[8],  (const float*)d_in[9],
                           (const float*)d_in[10], (const float*)d_in[11],
                           (const float*)d_in[12], (const float*)d_in[13],
                           (const float*)d_in[14], (const float*)d_in[15] };
    float* out = (float*)d_out;

    int N = in_sizes[0] / 128;
    int E = in_sizes[3];

    __half *xpeh, *a0, *a1, *xmh, *wb, *ws;
    float *dis0, *dis1;
    int *cnt, *off0, *off1, *cur0, *cur1;
    Edge8 *ent0, *ent1;
    cudaGetSymbolAddress((void**)&xpeh, g_xpeh);
    cudaGetSymbolAddress((void**)&a0,  g_a0);
    cudaGetSymbolAddress((void**)&a1,  g_a1);
    cudaGetSymbolAddress((void**)&xmh, g_xmh);
    cudaGetSymbolAddress((void**)&wb,  g_wb);
    cudaGetSymbolAddress((void**)&ws,  g_ws);
    cudaGetSymbolAddress((void**)&cnt, g_cnt);
    cudaGetSymbolAddress((void**)&off0, g_off0);
    cudaGetSymbolAddress((void**)&off1, g_off1);
    cudaGetSymbolAddress((void**)&cur0, g_cur0);
    cudaGetSymbolAddress((void**)&cur1, g_cur1);
    cudaGetSymbolAddress((void**)&dis0, g_dis0);
    cudaGetSymbolAddress((void**)&dis1, g_dis1);
    cudaGetSymbolAddress((void**)&ent0, g_ent0);
    cudaGetSymbolAddress((void**)&ent1, g_ent1);
    int* cnt0 = cnt;
    int* cnt1 = cnt + MAXN;

    cudaFuncSetAttribute((const void*)k_gemmBF,
                         cudaFuncAttributeMaxDynamicSharedMemorySize, SMEM_BF);
    cudaFuncSetAttribute((const void*)k_gemm2<true>,
                         cudaFuncAttributeMaxDynamicSharedMemorySize, SMEM_DF);
    cudaFuncSetAttribute((const void*)k_gemm2<false>,
                         cudaFuncAttributeMaxDynamicSharedMemorySize, SMEM_DF);

    static cudaStream_t s1 = nullptr;
    static cudaEvent_t ev[2];
    if (s1 == nullptr) {
        cudaStreamCreateWithFlags(&s1, cudaStreamNonBlocking);
        for (int i = 0; i < 2; i++) cudaEventCreateWithFlags(&ev[i], cudaEventDisableTiming);
    }

    int eb = (E + 255) / 256;
    int mtiles = (N + 127) / 128;
    int gw = (N + 7) / 8;

    // ======== fork: preprocessing + ws prep on s1 ========
    cudaEventRecord(ev[0], 0);
    cudaStreamWaitEvent(s1, ev[0], 0);

    cudaMemsetAsync(cnt, 0, 2 * MAXN * sizeof(int), s1);
    k_count2<<<dim3(eb, 2), 256, 0, s1>>>(ei0 + E, ei1 + E, cnt0, cnt1, E);
    k_scan2<<<2, 1024, 0, s1>>>(cnt0, cnt1, off0, off1, cur0, cur1, dis0, dis1, N);
    k_fill2<<<dim3(eb, 2), 256, 0, s1>>>(ei0, ea0, ei1, ea1, dis0, dis1,
                                         cur0, cur1, ent0, ent1, E);
    k_wtstk4<<<dim3(128, 4), 256, 0, s1>>>(lw[0], lw[1], lw[2], lw[3],
                                           lw[4], lw[5], lw[6], lw[7], ws);
    cudaEventRecord(ev[1], s1);

    // main: wcat prep + fused stage B (A constructed in-kernel)
    k_wtcat<<<256, 256>>>(nl1, nl2, wb);
    k_gemmBF<<<dim3(2, mtiles), 256, SMEM_BF>>>(x, pe, wb, xpeh, N);
    cudaStreamWaitEvent(0, ev[1], 0);   // join preprocessing + ws

    // ======== stage C: both graphs in one launch ========
    k_gather2<<<dim3(gw, 2), 256>>>(xpeh, 256, 128, off0, off1, ent0, ent1,
                                    dis0, dis1, a0, a1, N);

    // ======== stage D (fused dual-source GEMM, fp16 xm output) ========
    {
        GArgs a = {};
        a.A[0] = a0; a.A[1] = a1;
        a.B[0] = ws + 0 * 32768;
        a.B[1] = ws + 1 * 32768;
        a.C = xmh; a.M = N; a.NC = 128;
        k_gemm2<true><<<dim3(2, mtiles), 256, SMEM_DF>>>(a);
    }

    // ======== stage E ========
    k_gather2<<<dim3(gw, 2), 256>>>(xmh, 128, 0, off0, off1, ent0, ent1,
                                    dis0, dis1, a0, a1, N);

    // ======== stage F (fused dual-source GEMM, fp32 out) ========
    {
        GArgs a = {};
        a.A[0] = a0; a.A[1] = a1;
        a.B[0] = ws + 2 * 32768;
        a.B[1] = ws + 3 * 32768;
        a.C = out; a.M = N; a.NC = 128;
        k_gemm2<false><<<dim3(2, mtiles), 256, SMEM_DF>>>(a);
    }
}